// round 4
// baseline (speedup 1.0000x reference)
#include <cuda_runtime.h>
#include <math.h>

#define NTOK 1024
#define HID  1024
#define FFN  2048
#define NEXP 32
#define TOPK 4
#define NPAIR (NTOK*TOPK)

// ---------------- device scratch (static globals: no allocation) ----------------
static __device__ int   g_top_idx[NPAIR];
static __device__ float g_top_w[NPAIR];
static __device__ int   g_cnt[NEXP];
static __device__ int   g_off[NEXP + 1];
static __device__ int   g_pair_tok[NPAIR];
static __device__ float g_pair_w[NPAIR];
static __device__ float g_probs[NEXP];
static __device__ float g_H[(size_t)NPAIR * FFN];   // 32 MB intermediate activations

// ---------------- zero init (out is poisoned; accumulators must reset per replay) ----
__global__ void zero_kernel(float* out, int nd) {
    int i = blockIdx.x * blockDim.x + threadIdx.x;
    if (i < nd) out[i] = 0.0f;
    if (i < NEXP) { g_probs[i] = 0.0f; g_cnt[i] = 0; }
}

// ---------------- router: logits, top-4, softmax weights, aux stats ----------------
__global__ __launch_bounds__(256) void router_kernel(const float* __restrict__ x,
                                                     const float* __restrict__ gw,
                                                     const float* __restrict__ gb) {
    __shared__ float xs[HID];
    __shared__ float ps[256];
    __shared__ float ls[NEXP];
    int t = blockIdx.x, tid = threadIdx.x;
    for (int i = tid; i < HID; i += 256) xs[i] = x[(size_t)t * HID + i];
    __syncthreads();

    int e = tid & 31, c = tid >> 5;            // 32 experts x 8 chunks
    int base = c * (HID / 8);
    float s = 0.0f;
    for (int i = 0; i < HID / 8; i++)
        s += xs[base + i] * gw[(size_t)(base + i) * NEXP + e];
    ps[tid] = s;
    __syncthreads();

    if (tid < NEXP) {
        float v = gb[tid];
        #pragma unroll
        for (int c2 = 0; c2 < 8; c2++) v += ps[c2 * 32 + tid];
        ls[tid] = v;
    }
    __syncthreads();

    if (tid == 0) {
        float lv[NEXP];
        #pragma unroll
        for (int i = 0; i < NEXP; i++) lv[i] = ls[i];
        // exact top-4, ties -> lowest index (matches jax.lax.top_k)
        bool used[NEXP];
        #pragma unroll
        for (int i = 0; i < NEXP; i++) used[i] = false;
        int   idx[TOPK];
        float val[TOPK];
        for (int j = 0; j < TOPK; j++) {
            float best = -1e30f; int bi = 0;
            for (int i = 0; i < NEXP; i++)
                if (!used[i] && lv[i] > best) { best = lv[i]; bi = i; }
            used[bi] = true; idx[j] = bi; val[j] = best;
        }
        // softmax over selected logits
        float m = val[0], se = 0.0f, w[TOPK];
        #pragma unroll
        for (int j = 0; j < TOPK; j++) { w[j] = expf(val[j] - m); se += w[j]; }
        #pragma unroll
        for (int j = 0; j < TOPK; j++) {
            w[j] /= se;
            g_top_idx[t * TOPK + j] = idx[j];
            g_top_w[t * TOPK + j]   = w[j];
            atomicAdd(&g_cnt[idx[j]], 1);
        }
        // full softmax -> probs mean accumulators
        float mm = lv[0];
        for (int i = 1; i < NEXP; i++) mm = fmaxf(mm, lv[i]);
        float ss = 0.0f;
        for (int i = 0; i < NEXP; i++) ss += expf(lv[i] - mm);
        for (int i = 0; i < NEXP; i++)
            atomicAdd(&g_probs[i], expf(lv[i] - mm) / ss);
    }
}

// ---------------- prefix scan + aux loss ----------------
__global__ void scan_aux_kernel(const float* __restrict__ load_ema,
                                float* out, int out_size) {
    if (threadIdx.x != 0 || blockIdx.x != 0) return;
    int off = 0;
    for (int e = 0; e < NEXP; e++) { g_off[e] = off; off += g_cnt[e]; }
    g_off[NEXP] = off;

    float base_aux = 0.0f;
    for (int e = 0; e < NEXP; e++) {
        float frac = (float)g_cnt[e] / (float)NPAIR;   // counts.mean / top_k
        float pm   = g_probs[e] / (float)NTOK;
        base_aux += frac * pm;
    }
    base_aux *= (float)NEXP;

    float ssum = 0.0f;
    for (int e = 0; e < NEXP; e++) ssum += load_ema[e];
    float ent = 0.0f;
    for (int e = 0; e < NEXP; e++) {
        float lp = load_ema[e] / (ssum + 1e-8f);
        ent -= lp * logf(lp + 1e-8f);
    }
    float reg = logf((float)NEXP) - ent;
    float aux = base_aux + 0.001f * reg;
    if (out_size > NTOK * HID) out[NTOK * HID] = aux;
}

// ---------------- deterministic scatter: stable order within each expert ----------------
__global__ void scatter_kernel() {
    int e = threadIdx.x;
    if (e >= NEXP) return;
    int pos = g_off[e];
    for (int p = 0; p < NPAIR; p++) {
        if (g_top_idx[p] == e) {
            g_pair_tok[pos] = p >> 2;
            g_pair_w[pos]   = g_top_w[p];
            pos++;
        }
    }
}

// ---------------- f1: H = gelu(Xg @ W1[e] + b1[e]) ----------------
// grid: (FFN/128, NEXP); block 256; 64x128 tile, KB=8, 4x8 micro-tile
__global__ __launch_bounds__(256) void f1_kernel(const float* __restrict__ x,
                                                 const float* __restrict__ w1,
                                                 const float* __restrict__ b1) {
    int e  = blockIdx.y;
    int n0 = blockIdx.x * 128;
    int off = g_off[e];
    int cnt = g_off[e + 1] - off;
    if (cnt == 0) return;

    __shared__ float As[8][65];
    __shared__ float Bs[8][128];
    __shared__ int   stok[64];

    int tid = threadIdx.x;
    int tx = tid & 15, ty = tid >> 4;
    int rb = ty * 4, cb = tx * 8;
    const float* w1e = w1 + (size_t)e * HID * FFN;

    int ntiles = (cnt + 63) >> 6;
    for (int mt = 0; mt < ntiles; mt++) {
        int m0 = mt * 64;
        __syncthreads();   // protect stok from still-running previous-tile readers
        if (tid < 64) {
            int r = m0 + tid;
            stok[tid] = g_pair_tok[off + min(r, cnt - 1)];
        }
        __syncthreads();

        float acc[4][8];
        #pragma unroll
        for (int i = 0; i < 4; i++)
            #pragma unroll
            for (int j = 0; j < 8; j++) acc[i][j] = 0.0f;

        for (int k0 = 0; k0 < HID; k0 += 8) {
            #pragma unroll
            for (int p = 0; p < 2; p++) {
                int lin = tid + p * 256;
                int m = lin >> 3, kk = lin & 7;
                As[kk][m] = x[(size_t)stok[m] * HID + k0 + kk];
            }
            #pragma unroll
            for (int p = 0; p < 4; p++) {
                int lin = tid + p * 256;
                int kk = lin >> 7, n = lin & 127;
                Bs[kk][n] = w1e[(size_t)(k0 + kk) * FFN + n0 + n];
            }
            __syncthreads();
            #pragma unroll
            for (int kk = 0; kk < 8; kk++) {
                float a[4];
                #pragma unroll
                for (int i = 0; i < 4; i++) a[i] = As[kk][rb + i];
                float4 bv0 = *(const float4*)&Bs[kk][cb];
                float4 bv1 = *(const float4*)&Bs[kk][cb + 4];
                float b[8] = {bv0.x, bv0.y, bv0.z, bv0.w, bv1.x, bv1.y, bv1.z, bv1.w};
                #pragma unroll
                for (int i = 0; i < 4; i++)
                    #pragma unroll
                    for (int j = 0; j < 8; j++) acc[i][j] += a[i] * b[j];
            }
            __syncthreads();
        }
        // epilogue: bias + exact-erf GELU -> scratch
        #pragma unroll
        for (int i = 0; i < 4; i++) {
            int r = m0 + rb + i;
            if (r < cnt) {
                size_t row = (size_t)(off + r) * FFN;
                #pragma unroll
                for (int j = 0; j < 8; j++) {
                    int n = n0 + cb + j;
                    float v = acc[i][j] + b1[e * FFN + n];
                    g_H[row + n] = 0.5f * v * (1.0f + erff(v * 0.70710678118654752f));
                }
            }
        }
    }
}

// ---------------- f2: out += w * (H @ W2[e] + b2[e]) ----------------
// grid: (HID/128, NEXP)
__global__ __launch_bounds__(256) void f2_kernel(const float* __restrict__ w2,
                                                 const float* __restrict__ b2,
                                                 float* __restrict__ out) {
    int e  = blockIdx.y;
    int n0 = blockIdx.x * 128;
    int off = g_off[e];
    int cnt = g_off[e + 1] - off;
    if (cnt == 0) return;

    __shared__ float As[8][65];
    __shared__ float Bs[8][128];
    __shared__ int   stok[64];
    __shared__ float sw[64];
    __shared__ int   srow[64];

    int tid = threadIdx.x;
    int tx = tid & 15, ty = tid >> 4;
    int rb = ty * 4, cb = tx * 8;
    const float* w2e = w2 + (size_t)e * FFN * HID;

    int ntiles = (cnt + 63) >> 6;
    for (int mt = 0; mt < ntiles; mt++) {
        int m0 = mt * 64;
        __syncthreads();   // FIX: epilogue of previous tile reads stok/sw — must
                           // complete before tid<64 overwrites them (was the
                           // rel_err=8e-3 race)
        if (tid < 64) {
            int r  = m0 + tid;
            int rc = min(r, cnt - 1);
            srow[tid] = off + rc;
            stok[tid] = g_pair_tok[off + rc];
            sw[tid]   = g_pair_w[off + rc];
        }
        __syncthreads();

        float acc[4][8];
        #pragma unroll
        for (int i = 0; i < 4; i++)
            #pragma unroll
            for (int j = 0; j < 8; j++) acc[i][j] = 0.0f;

        for (int k0 = 0; k0 < FFN; k0 += 8) {
            #pragma unroll
            for (int p = 0; p < 2; p++) {
                int lin = tid + p * 256;
                int m = lin >> 3, kk = lin & 7;
                As[kk][m] = g_H[(size_t)srow[m] * FFN + k0 + kk];
            }
            #pragma unroll
            for (int p = 0; p < 4; p++) {
                int lin = tid + p * 256;
                int kk = lin >> 7, n = lin & 127;
                Bs[kk][n] = w2e[(size_t)(k0 + kk) * HID + n0 + n];
            }
            __syncthreads();
            #pragma unroll
            for (int kk = 0; kk < 8; kk++) {
                float a[4];
                #pragma unroll
                for (int i = 0; i < 4; i++) a[i] = As[kk][rb + i];
                float4 bv0 = *(const float4*)&Bs[kk][cb];
                float4 bv1 = *(const float4*)&Bs[kk][cb + 4];
                float b[8] = {bv0.x, bv0.y, bv0.z, bv0.w, bv1.x, bv1.y, bv1.z, bv1.w};
                #pragma unroll
                for (int i = 0; i < 4; i++)
                    #pragma unroll
                    for (int j = 0; j < 8; j++) acc[i][j] += a[i] * b[j];
            }
            __syncthreads();
        }
        // epilogue: bias + combine-weight scaled scatter-add
        #pragma unroll
        for (int i = 0; i < 4; i++) {
            int r = m0 + rb + i;
            if (r < cnt) {
                int   tok = stok[rb + i];
                float wgt = sw[rb + i];
                #pragma unroll
                for (int j = 0; j < 8; j++) {
                    int n = n0 + cb + j;
                    float y = acc[i][j] + b2[e * HID + n];
                    atomicAdd(&out[(size_t)tok * HID + n], wgt * y);
                }
            }
        }
    }
}

// ---------------- launch ----------------
extern "C" void kernel_launch(void* const* d_in, const int* in_sizes, int n_in,
                              void* d_out, int out_size) {
    const float* x        = (const float*)d_in[0];
    const float* gate_w   = (const float*)d_in[1];
    const float* gate_b   = (const float*)d_in[2];
    const float* w1       = (const float*)d_in[3];
    const float* b1       = (const float*)d_in[4];
    const float* w2       = (const float*)d_in[5];
    const float* b2       = (const float*)d_in[6];
    const float* load_ema = (const float*)d_in[7];
    float* out = (float*)d_out;

    int nd = NTOK * HID;
    zero_kernel<<<(nd + 255) / 256, 256>>>(out, nd);
    router_kernel<<<NTOK, 256>>>(x, gate_w, gate_b);
    scan_aux_kernel<<<1, 32>>>(load_ema, out, out_size);
    scatter_kernel<<<1, 32>>>();
    f1_kernel<<<dim3(FFN / 128, NEXP), 256>>>(x, w1, b1);
    f2_kernel<<<dim3(HID / 128, NEXP), 256>>>(w2, b2, out);
}

// round 6
// speedup vs baseline: 4.4520x; 4.4520x over previous
#include <cuda_runtime.h>
#include <cuda_bf16.h>
#include <math.h>
#include <stdint.h>

#define NTOK 1024
#define HID  1024
#define FFN  2048
#define NEXP 32
#define TOPK 4
#define NPAIR (NTOK*TOPK)

// ---------------- device scratch ----------------
static __device__ int      g_top_idx[NPAIR];
static __device__ float    g_top_w[NPAIR];
static __device__ int      g_cnt[NEXP];
static __device__ int      g_cnt2[NEXP];
static __device__ int      g_off[NEXP + 1];
static __device__ int      g_pair_tok[NPAIR];
static __device__ float    g_pair_w[NPAIR];
static __device__ int      g_slot[NPAIR];
static __device__ float    g_probs[NEXP];
static __device__ uint32_t g_H[(size_t)NPAIR * FFN];  // packed (bf16 hi | bf16 lo<<16)
static __device__ float    g_Y[(size_t)NPAIR * HID];  // per-slot f2 output

// smem strides (words) chosen conflict-free for fragment LDS patterns
#define ASTRIDE 12    // 8 data words (16 bf16-pairs) + 4 pad
#define BSTRIDE 136   // 128 data words + 8 pad

__device__ __forceinline__ void mma16816(float* c, const uint32_t* a,
                                         uint32_t b0, uint32_t b1) {
    asm volatile(
        "mma.sync.aligned.m16n8k16.row.col.f32.bf16.bf16.f32 "
        "{%0,%1,%2,%3}, {%4,%5,%6,%7}, {%8,%9}, {%0,%1,%2,%3};\n"
        : "+f"(c[0]), "+f"(c[1]), "+f"(c[2]), "+f"(c[3])
        : "r"(a[0]), "r"(a[1]), "r"(a[2]), "r"(a[3]), "r"(b0), "r"(b1));
}

// pack bf16(a)|bf16(b)<<16 hi, and residuals lo
__device__ __forceinline__ void split2(float a, float b, uint32_t& h, uint32_t& l) {
    __nv_bfloat16 ah = __float2bfloat16(a), bh = __float2bfloat16(b);
    float ar = a - __bfloat162float(ah), br = b - __bfloat162float(bh);
    __nv_bfloat16 al = __float2bfloat16(ar), bl = __float2bfloat16(br);
    h = (uint32_t)__bfloat16_as_ushort(ah) | ((uint32_t)__bfloat16_as_ushort(bh) << 16);
    l = (uint32_t)__bfloat16_as_ushort(al) | ((uint32_t)__bfloat16_as_ushort(bl) << 16);
}

// ---------------- small kernels ----------------
__global__ void zero_kernel() {
    int i = threadIdx.x;
    if (i < NEXP) { g_probs[i] = 0.0f; g_cnt[i] = 0; g_cnt2[i] = 0; }
}

__global__ __launch_bounds__(256) void router_kernel(const float* __restrict__ x,
                                                     const float* __restrict__ gw,
                                                     const float* __restrict__ gb) {
    __shared__ float xs[HID];
    __shared__ float ps[256];
    __shared__ float ls[NEXP];
    int t = blockIdx.x, tid = threadIdx.x;
    for (int i = tid; i < HID; i += 256) xs[i] = x[(size_t)t * HID + i];
    __syncthreads();
    int e = tid & 31, c = tid >> 5;
    int base = c * (HID / 8);
    float s = 0.0f;
    for (int i = 0; i < HID / 8; i++)
        s += xs[base + i] * gw[(size_t)(base + i) * NEXP + e];
    ps[tid] = s;
    __syncthreads();
    if (tid < NEXP) {
        float v = gb[tid];
        #pragma unroll
        for (int c2 = 0; c2 < 8; c2++) v += ps[c2 * 32 + tid];
        ls[tid] = v;
    }
    __syncthreads();
    if (tid == 0) {
        float lv[NEXP];
        #pragma unroll
        for (int i = 0; i < NEXP; i++) lv[i] = ls[i];
        bool used[NEXP];
        #pragma unroll
        for (int i = 0; i < NEXP; i++) used[i] = false;
        int idx[TOPK]; float val[TOPK];
        for (int j = 0; j < TOPK; j++) {
            float best = -1e30f; int bi = 0;
            for (int i = 0; i < NEXP; i++)
                if (!used[i] && lv[i] > best) { best = lv[i]; bi = i; }
            used[bi] = true; idx[j] = bi; val[j] = best;
        }
        float m = val[0], se = 0.0f, w[TOPK];
        #pragma unroll
        for (int j = 0; j < TOPK; j++) { w[j] = expf(val[j] - m); se += w[j]; }
        #pragma unroll
        for (int j = 0; j < TOPK; j++) {
            w[j] /= se;
            g_top_idx[t * TOPK + j] = idx[j];
            g_top_w[t * TOPK + j] = w[j];
            atomicAdd(&g_cnt[idx[j]], 1);
        }
        float mm = lv[0];
        for (int i = 1; i < NEXP; i++) mm = fmaxf(mm, lv[i]);
        float ss = 0.0f;
        for (int i = 0; i < NEXP; i++) ss += expf(lv[i] - mm);
        for (int i = 0; i < NEXP; i++)
            atomicAdd(&g_probs[i], expf(lv[i] - mm) / ss);
    }
}

__global__ void scan_aux_kernel(const float* __restrict__ load_ema,
                                float* out, int out_size) {
    if (threadIdx.x != 0 || blockIdx.x != 0) return;
    int off = 0;
    for (int e = 0; e < NEXP; e++) { g_off[e] = off; off += g_cnt[e]; }
    g_off[NEXP] = off;
    float base_aux = 0.0f;
    for (int e = 0; e < NEXP; e++)
        base_aux += ((float)g_cnt[e] / (float)NPAIR) * (g_probs[e] / (float)NTOK);
    base_aux *= (float)NEXP;
    float ssum = 0.0f;
    for (int e = 0; e < NEXP; e++) ssum += load_ema[e];
    float ent = 0.0f;
    for (int e = 0; e < NEXP; e++) {
        float lp = load_ema[e] / (ssum + 1e-8f);
        ent -= lp * logf(lp + 1e-8f);
    }
    float aux = base_aux + 0.001f * (logf((float)NEXP) - ent);
    if (out_size > NTOK * HID) out[NTOK * HID] = aux;
}

__global__ void scatter_kernel() {
    int p = blockIdx.x * 256 + threadIdx.x;
    if (p >= NPAIR) return;
    int e = g_top_idx[p];
    int pos = g_off[e] + atomicAdd(&g_cnt2[e], 1);
    g_pair_tok[pos] = p >> 2;
    g_pair_w[pos] = g_top_w[p];
    g_slot[p] = pos;
}

__global__ __launch_bounds__(256) void combine_kernel(float* __restrict__ out) {
    int t = blockIdx.x;
    int s0 = g_slot[t * 4 + 0], s1 = g_slot[t * 4 + 1];
    int s2 = g_slot[t * 4 + 2], s3 = g_slot[t * 4 + 3];
    for (int c = threadIdx.x; c < HID; c += 256)
        out[(size_t)t * HID + c] = g_Y[(size_t)s0 * HID + c] + g_Y[(size_t)s1 * HID + c] +
                                   g_Y[(size_t)s2 * HID + c] + g_Y[(size_t)s3 * HID + c];
}

// ---------------- f1: H = gelu(Xg @ W1[e] + b1) via mma.sync bf16x3 ----------------
// grid (FFN/128, NEXP, 2), block 256 (8 warps: 4m x 2n), block tile 128x128, K-step 16
__global__ __launch_bounds__(256) void f1_kernel(const float* __restrict__ x,
                                                 const float* __restrict__ w1,
                                                 const float* __restrict__ b1) {
    __shared__ uint32_t AsH[128 * ASTRIDE], AsL[128 * ASTRIDE];
    __shared__ uint32_t BsH[8 * BSTRIDE],   BsL[8 * BSTRIDE];

    int e = blockIdx.y, z = blockIdx.z;
    int off = g_off[e], cnt = g_off[e + 1] - off;
    if (cnt == 0 || z * 128 >= cnt) return;

    int tid = threadIdx.x, lane = tid & 31, wid = tid >> 5;
    int wm = wid & 3, wn = wid >> 2;
    int gg = lane >> 2, tt = lane & 3;
    int n0 = blockIdx.x * 128;
    const float* w1e = w1 + (size_t)e * HID * FFN;
    const float* b1e = b1 + (size_t)e * FFN;

    // A tasks: 2 per thread (q = tid, tid+256): row m = q>>2, quad fq = q&3
    // B task: 1 per thread: j = tid>>5 (k-pair row), nq = tid&31 (4-col group)
    int bj = tid >> 5, bnq = tid & 31;
    const float* bbase = w1e + (size_t)(2 * bj) * FFN + n0 + 4 * bnq;

    for (int m0 = z * 128; m0 < cnt; m0 += 256) {
        const float* aptr[2];
        int am[2], afq[2];
        #pragma unroll
        for (int it = 0; it < 2; it++) {
            int q = tid + it * 256;
            am[it] = q >> 2; afq[it] = q & 3;
            int slot = off + min(m0 + am[it], cnt - 1);
            aptr[it] = x + (size_t)g_pair_tok[slot] * HID + afq[it] * 4;
        }

        float acc[2][8][4];
        #pragma unroll
        for (int i = 0; i < 2; i++)
            #pragma unroll
            for (int j = 0; j < 8; j++)
                #pragma unroll
                for (int k = 0; k < 4; k++) acc[i][j][k] = 0.0f;

        float4 pa[2], pbu, pbv;
        #pragma unroll
        for (int it = 0; it < 2; it++) pa[it] = *(const float4*)(aptr[it]);
        pbu = *(const float4*)(bbase);
        pbv = *(const float4*)(bbase + FFN);

        const int NK = HID / 16;
        for (int kc = 0; kc < NK; kc++) {
            // ---- STS staged regs
            #pragma unroll
            for (int it = 0; it < 2; it++) {
                uint32_t h0, l0, h1, l1;
                split2(pa[it].x, pa[it].y, h0, l0);
                split2(pa[it].z, pa[it].w, h1, l1);
                int o = am[it] * ASTRIDE + 2 * afq[it];
                *(uint2*)&AsH[o] = make_uint2(h0, h1);
                *(uint2*)&AsL[o] = make_uint2(l0, l1);
            }
            {
                uint32_t h[4], l[4];
                split2(pbu.x, pbv.x, h[0], l[0]);
                split2(pbu.y, pbv.y, h[1], l[1]);
                split2(pbu.z, pbv.z, h[2], l[2]);
                split2(pbu.w, pbv.w, h[3], l[3]);
                int o = bj * BSTRIDE + 4 * bnq;
                *(uint4*)&BsH[o] = make_uint4(h[0], h[1], h[2], h[3]);
                *(uint4*)&BsL[o] = make_uint4(l[0], l[1], l[2], l[3]);
            }
            __syncthreads();

            // ---- prefetch next k-step
            if (kc + 1 < NK) {
                int k0n = (kc + 1) * 16;
                #pragma unroll
                for (int it = 0; it < 2; it++) pa[it] = *(const float4*)(aptr[it] + k0n);
                pbu = *(const float4*)(bbase + (size_t)k0n * FFN);
                pbv = *(const float4*)(bbase + (size_t)(k0n + 1) * FFN);
            }

            // ---- compute 48 HMMA
            uint32_t ah[2][4], al[2][4];
            #pragma unroll
            for (int mt = 0; mt < 2; mt++) {
                int mb = wm * 32 + mt * 16;
                ah[mt][0] = AsH[(mb + gg) * ASTRIDE + tt];
                ah[mt][1] = AsH[(mb + 8 + gg) * ASTRIDE + tt];
                ah[mt][2] = AsH[(mb + gg) * ASTRIDE + tt + 4];
                ah[mt][3] = AsH[(mb + 8 + gg) * ASTRIDE + tt + 4];
                al[mt][0] = AsL[(mb + gg) * ASTRIDE + tt];
                al[mt][1] = AsL[(mb + 8 + gg) * ASTRIDE + tt];
                al[mt][2] = AsL[(mb + gg) * ASTRIDE + tt + 4];
                al[mt][3] = AsL[(mb + 8 + gg) * ASTRIDE + tt + 4];
            }
            #pragma unroll
            for (int nt = 0; nt < 8; nt++) {
                int n = wn * 64 + nt * 8 + gg;
                uint32_t bh0 = BsH[tt * BSTRIDE + n], bh1 = BsH[(tt + 4) * BSTRIDE + n];
                uint32_t bl0 = BsL[tt * BSTRIDE + n], bl1 = BsL[(tt + 4) * BSTRIDE + n];
                #pragma unroll
                for (int mt = 0; mt < 2; mt++) {
                    mma16816(acc[mt][nt], ah[mt], bh0, bh1);
                    mma16816(acc[mt][nt], ah[mt], bl0, bl1);
                    mma16816(acc[mt][nt], al[mt], bh0, bh1);
                }
            }
            __syncthreads();
        }

        // ---- epilogue: bias + exact GELU -> packed bf16 hi/lo
        #pragma unroll
        for (int mt = 0; mt < 2; mt++) {
            #pragma unroll
            for (int half = 0; half < 2; half++) {
                int r = m0 + wm * 32 + mt * 16 + half * 8 + gg;
                if (r < cnt) {
                    size_t hrow = (size_t)(off + r) * FFN;
                    #pragma unroll
                    for (int nt = 0; nt < 8; nt++) {
                        int col = n0 + wn * 64 + nt * 8 + 2 * tt;
                        float v0 = acc[mt][nt][half * 2 + 0] + b1e[col];
                        float v1 = acc[mt][nt][half * 2 + 1] + b1e[col + 1];
                        float g0 = 0.5f * v0 * (1.0f + erff(v0 * 0.70710678118654752f));
                        float g1 = 0.5f * v1 * (1.0f + erff(v1 * 0.70710678118654752f));
                        __nv_bfloat16 h0 = __float2bfloat16(g0);
                        __nv_bfloat16 h1 = __float2bfloat16(g1);
                        __nv_bfloat16 q0 = __float2bfloat16(g0 - __bfloat162float(h0));
                        __nv_bfloat16 q1 = __float2bfloat16(g1 - __bfloat162float(h1));
                        uint32_t p0 = (uint32_t)__bfloat16_as_ushort(h0) |
                                      ((uint32_t)__bfloat16_as_ushort(q0) << 16);
                        uint32_t p1 = (uint32_t)__bfloat16_as_ushort(h1) |
                                      ((uint32_t)__bfloat16_as_ushort(q1) << 16);
                        *(uint2*)&g_H[hrow + col] = make_uint2(p0, p1);
                    }
                }
            }
        }
    }
}

// ---------------- f2: Y[slot] = w * (H @ W2[e] + b2) via mma.sync bf16x3 ----------------
// grid (HID/128, NEXP, 2), block 256
__global__ __launch_bounds__(256) void f2_kernel(const float* __restrict__ w2,
                                                 const float* __restrict__ b2) {
    __shared__ uint32_t AsH[128 * ASTRIDE], AsL[128 * ASTRIDE];
    __shared__ uint32_t BsH[8 * BSTRIDE],   BsL[8 * BSTRIDE];

    int e = blockIdx.y, z = blockIdx.z;
    int off = g_off[e], cnt = g_off[e + 1] - off;
    if (cnt == 0 || z * 128 >= cnt) return;

    int tid = threadIdx.x, lane = tid & 31, wid = tid >> 5;
    int wm = wid & 3, wn = wid >> 2;
    int gg = lane >> 2, tt = lane & 3;
    int n0 = blockIdx.x * 128;
    const float* w2e = w2 + (size_t)e * FFN * HID;
    const float* b2e = b2 + (size_t)e * HID;

    int bj = tid >> 5, bnq = tid & 31;
    const float* bbase = w2e + (size_t)(2 * bj) * HID + n0 + 4 * bnq;

    for (int m0 = z * 128; m0 < cnt; m0 += 256) {
        const uint32_t* aptr[2];
        int am[2], afq[2];
        #pragma unroll
        for (int it = 0; it < 2; it++) {
            int q = tid + it * 256;
            am[it] = q >> 2; afq[it] = q & 3;
            int slot = off + min(m0 + am[it], cnt - 1);
            aptr[it] = g_H + (size_t)slot * FFN + afq[it] * 4;
        }

        float acc[2][8][4];
        #pragma unroll
        for (int i = 0; i < 2; i++)
            #pragma unroll
            for (int j = 0; j < 8; j++)
                #pragma unroll
                for (int k = 0; k < 4; k++) acc[i][j][k] = 0.0f;

        uint4 pa[2]; float4 pbu, pbv;
        #pragma unroll
        for (int it = 0; it < 2; it++) pa[it] = *(const uint4*)(aptr[it]);
        pbu = *(const float4*)(bbase);
        pbv = *(const float4*)(bbase + HID);

        const int NK = FFN / 16;
        for (int kc = 0; kc < NK; kc++) {
            #pragma unroll
            for (int it = 0; it < 2; it++) {
                // packed elems: hi = low16s, lo = high16s
                uint32_t h0 = __byte_perm(pa[it].x, pa[it].y, 0x5410);
                uint32_t l0 = __byte_perm(pa[it].x, pa[it].y, 0x7632);
                uint32_t h1 = __byte_perm(pa[it].z, pa[it].w, 0x5410);
                uint32_t l1 = __byte_perm(pa[it].z, pa[it].w, 0x7632);
                int o = am[it] * ASTRIDE + 2 * afq[it];
                *(uint2*)&AsH[o] = make_uint2(h0, h1);
                *(uint2*)&AsL[o] = make_uint2(l0, l1);
            }
            {
                uint32_t h[4], l[4];
                split2(pbu.x, pbv.x, h[0], l[0]);
                split2(pbu.y, pbv.y, h[1], l[1]);
                split2(pbu.z, pbv.z, h[2], l[2]);
                split2(pbu.w, pbv.w, h[3], l[3]);
                int o = bj * BSTRIDE + 4 * bnq;
                *(uint4*)&BsH[o] = make_uint4(h[0], h[1], h[2], h[3]);
                *(uint4*)&BsL[o] = make_uint4(l[0], l[1], l[2], l[3]);
            }
            __syncthreads();

            if (kc + 1 < NK) {
                int k0n = (kc + 1) * 16;
                #pragma unroll
                for (int it = 0; it < 2; it++) pa[it] = *(const uint4*)(aptr[it] + k0n);
                pbu = *(const float4*)(bbase + (size_t)k0n * HID);
                pbv = *(const float4*)(bbase + (size_t)(k0n + 1) * HID);
            }

            uint32_t ah[2][4], al[2][4];
            #pragma unroll
            for (int mt = 0; mt < 2; mt++) {
                int mb = wm * 32 + mt * 16;
                ah[mt][0] = AsH[(mb + gg) * ASTRIDE + tt];
                ah[mt][1] = AsH[(mb + 8 + gg) * ASTRIDE + tt];
                ah[mt][2] = AsH[(mb + gg) * ASTRIDE + tt + 4];
                ah[mt][3] = AsH[(mb + 8 + gg) * ASTRIDE + tt + 4];
                al[mt][0] = AsL[(mb + gg) * ASTRIDE + tt];
                al[mt][1] = AsL[(mb + 8 + gg) * ASTRIDE + tt];
                al[mt][2] = AsL[(mb + gg) * ASTRIDE + tt + 4];
                al[mt][3] = AsL[(mb + 8 + gg) * ASTRIDE + tt + 4];
            }
            #pragma unroll
            for (int nt = 0; nt < 8; nt++) {
                int n = wn * 64 + nt * 8 + gg;
                uint32_t bh0 = BsH[tt * BSTRIDE + n], bh1 = BsH[(tt + 4) * BSTRIDE + n];
                uint32_t bl0 = BsL[tt * BSTRIDE + n], bl1 = BsL[(tt + 4) * BSTRIDE + n];
                #pragma unroll
                for (int mt = 0; mt < 2; mt++) {
                    mma16816(acc[mt][nt], ah[mt], bh0, bh1);
                    mma16816(acc[mt][nt], ah[mt], bl0, bl1);
                    mma16816(acc[mt][nt], al[mt], bh0, bh1);
                }
            }
            __syncthreads();
        }

        // ---- epilogue: bias + combine weight -> g_Y
        #pragma unroll
        for (int mt = 0; mt < 2; mt++) {
            #pragma unroll
            for (int half = 0; half < 2; half++) {
                int r = m0 + wm * 32 + mt * 16 + half * 8 + gg;
                if (r < cnt) {
                    int slot = off + r;
                    float wgt = g_pair_w[slot];
                    size_t yrow = (size_t)slot * HID;
                    #pragma unroll
                    for (int nt = 0; nt < 8; nt++) {
                        int col = n0 + wn * 64 + nt * 8 + 2 * tt;
                        float y0 = wgt * (acc[mt][nt][half * 2 + 0] + b2e[col]);
                        float y1 = wgt * (acc[mt][nt][half * 2 + 1] + b2e[col + 1]);
                        *(float2*)&g_Y[yrow + col] = make_float2(y0, y1);
                    }
                }
            }
        }
    }
}

// ---------------- launch ----------------
extern "C" void kernel_launch(void* const* d_in, const int* in_sizes, int n_in,
                              void* d_out, int out_size) {
    const float* x        = (const float*)d_in[0];
    const float* gate_w   = (const float*)d_in[1];
    const float* gate_b   = (const float*)d_in[2];
    const float* w1       = (const float*)d_in[3];
    const float* b1       = (const float*)d_in[4];
    const float* w2       = (const float*)d_in[5];
    const float* b2       = (const float*)d_in[6];
    const float* load_ema = (const float*)d_in[7];
    float* out = (float*)d_out;

    zero_kernel<<<1, 32>>>();
    router_kernel<<<NTOK, 256>>>(x, gate_w, gate_b);
    scan_aux_kernel<<<1, 32>>>(load_ema, out, out_size);
    scatter_kernel<<<NPAIR / 256, 256>>>();
    f1_kernel<<<dim3(FFN / 128, NEXP, 2), 256>>>(x, w1, b1);
    f2_kernel<<<dim3(HID / 128, NEXP, 2), 256>>>(w2, b2);
    combine_kernel<<<NTOK, 256>>>(out);
}

// round 7
// speedup vs baseline: 4.6408x; 1.0424x over previous
#include <cuda_runtime.h>
#include <cuda_bf16.h>
#include <math.h>
#include <stdint.h>

#define NTOK 1024
#define HID  1024
#define FFN  2048
#define NEXP 32
#define TOPK 4
#define NPAIR (NTOK*TOPK)

// ---------------- device scratch ----------------
static __device__ int      g_top_idx[NPAIR];
static __device__ float    g_top_w[NPAIR];
static __device__ int      g_cnt[NEXP];
static __device__ int      g_cnt2[NEXP];
static __device__ int      g_off[NEXP + 1];
static __device__ int      g_pair_tok[NPAIR];
static __device__ float    g_pair_w[NPAIR];
static __device__ int      g_slot[NPAIR];
static __device__ float    g_probs[NEXP];
static __device__ uint32_t g_H[(size_t)NPAIR * FFN];  // packed (bf16 hi | bf16 lo<<16)
static __device__ float    g_Y[(size_t)NPAIR * HID];  // per-slot f2 output

#define ASTRIDE 12    // words per A row (8 data + 4 pad): ldmatrix granules 3m%8 distinct
#define BSTRIDE 136   // words per B k-pair row (128 data + 8 pad)

__device__ __forceinline__ void mma16816(float* c, const uint32_t* a,
                                         uint32_t b0, uint32_t b1) {
    asm volatile(
        "mma.sync.aligned.m16n8k16.row.col.f32.bf16.bf16.f32 "
        "{%0,%1,%2,%3}, {%4,%5,%6,%7}, {%8,%9}, {%0,%1,%2,%3};\n"
        : "+f"(c[0]), "+f"(c[1]), "+f"(c[2]), "+f"(c[3])
        : "r"(a[0]), "r"(a[1]), "r"(a[2]), "r"(a[3]), "r"(b0), "r"(b1));
}
__device__ __forceinline__ void ldm4(uint32_t* r, uint32_t saddr) {
    asm volatile("ldmatrix.sync.aligned.m8n8.x4.shared.b16 {%0,%1,%2,%3}, [%4];"
        : "=r"(r[0]), "=r"(r[1]), "=r"(r[2]), "=r"(r[3]) : "r"(saddr));
}

// cheap split: hi = truncated top-16s packed via PRMT; residual exact, packed via bf16x2 cvt
__device__ __forceinline__ void split2t(float a, float b, uint32_t& h, uint32_t& l) {
    uint32_t ua = __float_as_uint(a), ub = __float_as_uint(b);
    h = __byte_perm(ua, ub, 0x7632);   // {lo16 = a>>16, hi16 = b>>16}
    float ar = a - __uint_as_float(ua & 0xFFFF0000u);
    float br = b - __uint_as_float(ub & 0xFFFF0000u);
    asm("cvt.rn.bf16x2.f32 %0, %1, %2;" : "=r"(l) : "f"(br), "f"(ar));
}

// ---------------- small kernels ----------------
__global__ void zero_kernel() {
    int i = threadIdx.x;
    if (i < NEXP) { g_probs[i] = 0.0f; g_cnt[i] = 0; g_cnt2[i] = 0; }
}

__global__ __launch_bounds__(256) void router_kernel(const float* __restrict__ x,
                                                     const float* __restrict__ gw,
                                                     const float* __restrict__ gb) {
    __shared__ float xs[HID];
    __shared__ float ps[256];
    __shared__ float ls[NEXP];
    int t = blockIdx.x, tid = threadIdx.x;
    for (int i = tid; i < HID; i += 256) xs[i] = x[(size_t)t * HID + i];
    __syncthreads();
    int e = tid & 31, c = tid >> 5;
    int base = c * (HID / 8);
    float s = 0.0f;
    for (int i = 0; i < HID / 8; i++)
        s += xs[base + i] * gw[(size_t)(base + i) * NEXP + e];
    ps[tid] = s;
    __syncthreads();
    if (tid < NEXP) {
        float v = gb[tid];
        #pragma unroll
        for (int c2 = 0; c2 < 8; c2++) v += ps[c2 * 32 + tid];
        ls[tid] = v;
    }
    __syncthreads();
    if (tid == 0) {
        float lv[NEXP];
        #pragma unroll
        for (int i = 0; i < NEXP; i++) lv[i] = ls[i];
        bool used[NEXP];
        #pragma unroll
        for (int i = 0; i < NEXP; i++) used[i] = false;
        int idx[TOPK]; float val[TOPK];
        for (int j = 0; j < TOPK; j++) {
            float best = -1e30f; int bi = 0;
            for (int i = 0; i < NEXP; i++)
                if (!used[i] && lv[i] > best) { best = lv[i]; bi = i; }
            used[bi] = true; idx[j] = bi; val[j] = best;
        }
        float m = val[0], se = 0.0f, w[TOPK];
        #pragma unroll
        for (int j = 0; j < TOPK; j++) { w[j] = expf(val[j] - m); se += w[j]; }
        #pragma unroll
        for (int j = 0; j < TOPK; j++) {
            w[j] /= se;
            g_top_idx[t * TOPK + j] = idx[j];
            g_top_w[t * TOPK + j] = w[j];
            atomicAdd(&g_cnt[idx[j]], 1);
        }
        float mm = lv[0];
        for (int i = 1; i < NEXP; i++) mm = fmaxf(mm, lv[i]);
        float ss = 0.0f;
        for (int i = 0; i < NEXP; i++) ss += expf(lv[i] - mm);
        for (int i = 0; i < NEXP; i++)
            atomicAdd(&g_probs[i], expf(lv[i] - mm) / ss);
    }
}

__global__ void scan_aux_kernel(const float* __restrict__ load_ema,
                                float* out, int out_size) {
    if (threadIdx.x != 0 || blockIdx.x != 0) return;
    int off = 0;
    for (int e = 0; e < NEXP; e++) { g_off[e] = off; off += g_cnt[e]; }
    g_off[NEXP] = off;
    float base_aux = 0.0f;
    for (int e = 0; e < NEXP; e++)
        base_aux += ((float)g_cnt[e] / (float)NPAIR) * (g_probs[e] / (float)NTOK);
    base_aux *= (float)NEXP;
    float ssum = 0.0f;
    for (int e = 0; e < NEXP; e++) ssum += load_ema[e];
    float ent = 0.0f;
    for (int e = 0; e < NEXP; e++) {
        float lp = load_ema[e] / (ssum + 1e-8f);
        ent -= lp * logf(lp + 1e-8f);
    }
    float aux = base_aux + 0.001f * (logf((float)NEXP) - ent);
    if (out_size > NTOK * HID) out[NTOK * HID] = aux;
}

__global__ void scatter_kernel() {
    int p = blockIdx.x * 256 + threadIdx.x;
    if (p >= NPAIR) return;
    int e = g_top_idx[p];
    int pos = g_off[e] + atomicAdd(&g_cnt2[e], 1);
    g_pair_tok[pos] = p >> 2;
    g_pair_w[pos] = g_top_w[p];
    g_slot[p] = pos;
}

__global__ __launch_bounds__(256) void combine_kernel(float* __restrict__ out) {
    int t = blockIdx.x;
    int s0 = g_slot[t * 4 + 0], s1 = g_slot[t * 4 + 1];
    int s2 = g_slot[t * 4 + 2], s3 = g_slot[t * 4 + 3];
    for (int c = threadIdx.x; c < HID; c += 256)
        out[(size_t)t * HID + c] = g_Y[(size_t)s0 * HID + c] + g_Y[(size_t)s1 * HID + c] +
                                   g_Y[(size_t)s2 * HID + c] + g_Y[(size_t)s3 * HID + c];
}

// ---------------- f1: H = gelu(Xg @ W1[e] + b1) --------------------------------
// grid (FFN/128, NEXP, 2), block 256 (8 warps: 4m x 2n), tile 128x128, K-step 16,
// double-buffered smem, ldmatrix A-frags, truncation split.
__global__ __launch_bounds__(256) void f1_kernel(const float* __restrict__ x,
                                                 const float* __restrict__ w1,
                                                 const float* __restrict__ b1) {
    __shared__ uint32_t AsH[2][128 * ASTRIDE], AsL[2][128 * ASTRIDE];
    __shared__ uint32_t BsH[2][8 * BSTRIDE],   BsL[2][8 * BSTRIDE];

    int e = blockIdx.y, z = blockIdx.z;
    int off = g_off[e], cnt = g_off[e + 1] - off;
    if (cnt == 0 || z * 128 >= cnt) return;

    int tid = threadIdx.x, lane = tid & 31, wid = tid >> 5;
    int wm = wid & 3, wn = wid >> 2;
    int gg = lane >> 2, tt = lane & 3;
    int n0 = blockIdx.x * 128;
    const float* w1e = w1 + (size_t)e * HID * FFN;
    const float* b1e = b1 + (size_t)e * FFN;

    int bj = tid >> 5, bnq = tid & 31;
    const float* bbase = w1e + (size_t)(2 * bj) * FFN + n0 + 4 * bnq;

    // ldmatrix row offsets (bytes) per mt, stage-independent
    uint32_t ldmoff[2];
    #pragma unroll
    for (int mt = 0; mt < 2; mt++)
        ldmoff[mt] = (uint32_t)(((wm * 32 + mt * 16 + (lane & 15)) * ASTRIDE +
                                 (lane >> 4) * 4) * 4);
    uint32_t aHbase[2], aLbase[2];
    #pragma unroll
    for (int st = 0; st < 2; st++) {
        aHbase[st] = (uint32_t)__cvta_generic_to_shared(&AsH[st][0]);
        aLbase[st] = (uint32_t)__cvta_generic_to_shared(&AsL[st][0]);
    }

    const int NK = HID / 16;
    for (int m0 = z * 128; m0 < cnt; m0 += 256) {
        int am = tid >> 1, afq2 = (tid & 1) * 2;    // each thread: 1 row, 8 floats (2 quads)
        int slot = off + min(m0 + am, cnt - 1);
        const float* aptr = x + (size_t)g_pair_tok[slot] * HID + afq2 * 4;

        float acc[2][8][4];
        #pragma unroll
        for (int i = 0; i < 2; i++)
            #pragma unroll
            for (int j = 0; j < 8; j++)
                #pragma unroll
                for (int k = 0; k < 4; k++) acc[i][j][k] = 0.0f;

        float4 pa0, pa1, pbu, pbv;
        // prologue: load k0, fill stage 0, prefetch k1
        pa0 = *(const float4*)(aptr);
        pa1 = *(const float4*)(aptr + 4);
        pbu = *(const float4*)(bbase);
        pbv = *(const float4*)(bbase + FFN);
        {
            uint32_t h0, l0, h1, l1, h2, l2, h3, l3;
            split2t(pa0.x, pa0.y, h0, l0); split2t(pa0.z, pa0.w, h1, l1);
            split2t(pa1.x, pa1.y, h2, l2); split2t(pa1.z, pa1.w, h3, l3);
            int o = am * ASTRIDE + afq2 * 2;
            *(uint4*)&AsH[0][o] = make_uint4(h0, h1, h2, h3);
            *(uint4*)&AsL[0][o] = make_uint4(l0, l1, l2, l3);
            uint32_t bh[4], bl[4];
            split2t(pbu.x, pbv.x, bh[0], bl[0]); split2t(pbu.y, pbv.y, bh[1], bl[1]);
            split2t(pbu.z, pbv.z, bh[2], bl[2]); split2t(pbu.w, pbv.w, bh[3], bl[3]);
            int ob = bj * BSTRIDE + 4 * bnq;
            *(uint4*)&BsH[0][ob] = make_uint4(bh[0], bh[1], bh[2], bh[3]);
            *(uint4*)&BsL[0][ob] = make_uint4(bl[0], bl[1], bl[2], bl[3]);
        }
        pa0 = *(const float4*)(aptr + 16);
        pa1 = *(const float4*)(aptr + 20);
        pbu = *(const float4*)(bbase + (size_t)16 * FFN);
        pbv = *(const float4*)(bbase + (size_t)17 * FFN);
        __syncthreads();

        for (int kc = 0; kc < NK; kc++) {
            int cur = kc & 1, nxt = cur ^ 1;
            // stage k+1 STS from prefetched regs, then prefetch k+2
            if (kc + 1 < NK) {
                uint32_t h0, l0, h1, l1, h2, l2, h3, l3;
                split2t(pa0.x, pa0.y, h0, l0); split2t(pa0.z, pa0.w, h1, l1);
                split2t(pa1.x, pa1.y, h2, l2); split2t(pa1.z, pa1.w, h3, l3);
                int o = am * ASTRIDE + afq2 * 2;
                *(uint4*)&AsH[nxt][o] = make_uint4(h0, h1, h2, h3);
                *(uint4*)&AsL[nxt][o] = make_uint4(l0, l1, l2, l3);
                uint32_t bh[4], bl[4];
                split2t(pbu.x, pbv.x, bh[0], bl[0]); split2t(pbu.y, pbv.y, bh[1], bl[1]);
                split2t(pbu.z, pbv.z, bh[2], bl[2]); split2t(pbu.w, pbv.w, bh[3], bl[3]);
                int ob = bj * BSTRIDE + 4 * bnq;
                *(uint4*)&BsH[nxt][ob] = make_uint4(bh[0], bh[1], bh[2], bh[3]);
                *(uint4*)&BsL[nxt][ob] = make_uint4(bl[0], bl[1], bl[2], bl[3]);
            }
            if (kc + 2 < NK) {
                int k0n = (kc + 2) * 16;
                pa0 = *(const float4*)(aptr + k0n);
                pa1 = *(const float4*)(aptr + k0n + 4);
                pbu = *(const float4*)(bbase + (size_t)k0n * FFN);
                pbv = *(const float4*)(bbase + (size_t)(k0n + 1) * FFN);
            }
            // compute stage cur
            uint32_t ah[2][4], al[2][4];
            #pragma unroll
            for (int mt = 0; mt < 2; mt++) {
                ldm4(ah[mt], aHbase[cur] + ldmoff[mt]);
                ldm4(al[mt], aLbase[cur] + ldmoff[mt]);
            }
            #pragma unroll
            for (int nt = 0; nt < 8; nt++) {
                int n = wn * 64 + nt * 8 + gg;
                uint32_t bh0 = BsH[cur][tt * BSTRIDE + n], bh1 = BsH[cur][(tt + 4) * BSTRIDE + n];
                uint32_t bl0 = BsL[cur][tt * BSTRIDE + n], bl1 = BsL[cur][(tt + 4) * BSTRIDE + n];
                #pragma unroll
                for (int mt = 0; mt < 2; mt++) {
                    mma16816(acc[mt][nt], ah[mt], bh0, bh1);
                    mma16816(acc[mt][nt], ah[mt], bl0, bl1);
                    mma16816(acc[mt][nt], al[mt], bh0, bh1);
                }
            }
            __syncthreads();
        }

        // epilogue: bias + exact GELU -> packed bf16 hi/lo
        #pragma unroll
        for (int mt = 0; mt < 2; mt++) {
            #pragma unroll
            for (int half = 0; half < 2; half++) {
                int r = m0 + wm * 32 + mt * 16 + half * 8 + gg;
                if (r < cnt) {
                    size_t hrow = (size_t)(off + r) * FFN;
                    #pragma unroll
                    for (int nt = 0; nt < 8; nt++) {
                        int col = n0 + wn * 64 + nt * 8 + 2 * tt;
                        float v0 = acc[mt][nt][half * 2 + 0] + b1e[col];
                        float v1 = acc[mt][nt][half * 2 + 1] + b1e[col + 1];
                        float g0 = 0.5f * v0 * (1.0f + erff(v0 * 0.70710678118654752f));
                        float g1 = 0.5f * v1 * (1.0f + erff(v1 * 0.70710678118654752f));
                        uint32_t u0 = __float_as_uint(g0), u1 = __float_as_uint(g1);
                        float r0 = g0 - __uint_as_float(u0 & 0xFFFF0000u);
                        float r1 = g1 - __uint_as_float(u1 & 0xFFFF0000u);
                        uint32_t p0 = (u0 >> 16) |
                            ((uint32_t)__bfloat16_as_ushort(__float2bfloat16(r0)) << 16);
                        uint32_t p1 = (u1 >> 16) |
                            ((uint32_t)__bfloat16_as_ushort(__float2bfloat16(r1)) << 16);
                        *(uint2*)&g_H[hrow + col] = make_uint2(p0, p1);
                    }
                }
            }
        }
        if (m0 + 256 < cnt) __syncthreads();
    }
}

// ---------------- f2: Y[slot] = w * (H @ W2[e] + b2) ---------------------------
// grid (HID/128, NEXP, 2), block 256
__global__ __launch_bounds__(256) void f2_kernel(const float* __restrict__ w2,
                                                 const float* __restrict__ b2) {
    __shared__ uint32_t AsH[2][128 * ASTRIDE], AsL[2][128 * ASTRIDE];
    __shared__ uint32_t BsH[2][8 * BSTRIDE],   BsL[2][8 * BSTRIDE];

    int e = blockIdx.y, z = blockIdx.z;
    int off = g_off[e], cnt = g_off[e + 1] - off;
    if (cnt == 0 || z * 128 >= cnt) return;

    int tid = threadIdx.x, lane = tid & 31, wid = tid >> 5;
    int wm = wid & 3, wn = wid >> 2;
    int gg = lane >> 2, tt = lane & 3;
    int n0 = blockIdx.x * 128;
    const float* w2e = w2 + (size_t)e * FFN * HID;
    const float* b2e = b2 + (size_t)e * HID;

    int bj = tid >> 5, bnq = tid & 31;
    const float* bbase = w2e + (size_t)(2 * bj) * HID + n0 + 4 * bnq;

    uint32_t ldmoff[2];
    #pragma unroll
    for (int mt = 0; mt < 2; mt++)
        ldmoff[mt] = (uint32_t)(((wm * 32 + mt * 16 + (lane & 15)) * ASTRIDE +
                                 (lane >> 4) * 4) * 4);
    uint32_t aHbase[2], aLbase[2];
    #pragma unroll
    for (int st = 0; st < 2; st++) {
        aHbase[st] = (uint32_t)__cvta_generic_to_shared(&AsH[st][0]);
        aLbase[st] = (uint32_t)__cvta_generic_to_shared(&AsL[st][0]);
    }

    const int NK = FFN / 16;
    for (int m0 = z * 128; m0 < cnt; m0 += 256) {
        int am = tid >> 1, afq2 = (tid & 1) * 2;
        int slot = off + min(m0 + am, cnt - 1);
        const uint32_t* aptr = g_H + (size_t)slot * FFN + afq2 * 4;

        float acc[2][8][4];
        #pragma unroll
        for (int i = 0; i < 2; i++)
            #pragma unroll
            for (int j = 0; j < 8; j++)
                #pragma unroll
                for (int k = 0; k < 4; k++) acc[i][j][k] = 0.0f;

        uint4 pa0, pa1; float4 pbu, pbv;
        pa0 = *(const uint4*)(aptr);
        pa1 = *(const uint4*)(aptr + 4);
        pbu = *(const float4*)(bbase);
        pbv = *(const float4*)(bbase + HID);
        {
            int o = am * ASTRIDE + afq2 * 2;
            *(uint4*)&AsH[0][o] = make_uint4(
                __byte_perm(pa0.x, pa0.y, 0x5410), __byte_perm(pa0.z, pa0.w, 0x5410),
                __byte_perm(pa1.x, pa1.y, 0x5410), __byte_perm(pa1.z, pa1.w, 0x5410));
            *(uint4*)&AsL[0][o] = make_uint4(
                __byte_perm(pa0.x, pa0.y, 0x7632), __byte_perm(pa0.z, pa0.w, 0x7632),
                __byte_perm(pa1.x, pa1.y, 0x7632), __byte_perm(pa1.z, pa1.w, 0x7632));
            uint32_t bh[4], bl[4];
            split2t(pbu.x, pbv.x, bh[0], bl[0]); split2t(pbu.y, pbv.y, bh[1], bl[1]);
            split2t(pbu.z, pbv.z, bh[2], bl[2]); split2t(pbu.w, pbv.w, bh[3], bl[3]);
            int ob = bj * BSTRIDE + 4 * bnq;
            *(uint4*)&BsH[0][ob] = make_uint4(bh[0], bh[1], bh[2], bh[3]);
            *(uint4*)&BsL[0][ob] = make_uint4(bl[0], bl[1], bl[2], bl[3]);
        }
        pa0 = *(const uint4*)(aptr + 16);
        pa1 = *(const uint4*)(aptr + 20);
        pbu = *(const float4*)(bbase + (size_t)16 * HID);
        pbv = *(const float4*)(bbase + (size_t)17 * HID);
        __syncthreads();

        for (int kc = 0; kc < NK; kc++) {
            int cur = kc & 1, nxt = cur ^ 1;
            if (kc + 1 < NK) {
                int o = am * ASTRIDE + afq2 * 2;
                *(uint4*)&AsH[nxt][o] = make_uint4(
                    __byte_perm(pa0.x, pa0.y, 0x5410), __byte_perm(pa0.z, pa0.w, 0x5410),
                    __byte_perm(pa1.x, pa1.y, 0x5410), __byte_perm(pa1.z, pa1.w, 0x5410));
                *(uint4*)&AsL[nxt][o] = make_uint4(
                    __byte_perm(pa0.x, pa0.y, 0x7632), __byte_perm(pa0.z, pa0.w, 0x7632),
                    __byte_perm(pa1.x, pa1.y, 0x7632), __byte_perm(pa1.z, pa1.w, 0x7632));
                uint32_t bh[4], bl[4];
                split2t(pbu.x, pbv.x, bh[0], bl[0]); split2t(pbu.y, pbv.y, bh[1], bl[1]);
                split2t(pbu.z, pbv.z, bh[2], bl[2]); split2t(pbu.w, pbv.w, bh[3], bl[3]);
                int ob = bj * BSTRIDE + 4 * bnq;
                *(uint4*)&BsH[nxt][ob] = make_uint4(bh[0], bh[1], bh[2], bh[3]);
                *(uint4*)&BsL[nxt][ob] = make_uint4(bl[0], bl[1], bl[2], bl[3]);
            }
            if (kc + 2 < NK) {
                int k0n = (kc + 2) * 16;
                pa0 = *(const uint4*)(aptr + k0n);
                pa1 = *(const uint4*)(aptr + k0n + 4);
                pbu = *(const float4*)(bbase + (size_t)k0n * HID);
                pbv = *(const float4*)(bbase + (size_t)(k0n + 1) * HID);
            }
            uint32_t ah[2][4], al[2][4];
            #pragma unroll
            for (int mt = 0; mt < 2; mt++) {
                ldm4(ah[mt], aHbase[cur] + ldmoff[mt]);
                ldm4(al[mt], aLbase[cur] + ldmoff[mt]);
            }
            #pragma unroll
            for (int nt = 0; nt < 8; nt++) {
                int n = wn * 64 + nt * 8 + gg;
                uint32_t bh0 = BsH[cur][tt * BSTRIDE + n], bh1 = BsH[cur][(tt + 4) * BSTRIDE + n];
                uint32_t bl0 = BsL[cur][tt * BSTRIDE + n], bl1 = BsL[cur][(tt + 4) * BSTRIDE + n];
                #pragma unroll
                for (int mt = 0; mt < 2; mt++) {
                    mma16816(acc[mt][nt], ah[mt], bh0, bh1);
                    mma16816(acc[mt][nt], ah[mt], bl0, bl1);
                    mma16816(acc[mt][nt], al[mt], bh0, bh1);
                }
            }
            __syncthreads();
        }

        // epilogue: bias + combine weight -> g_Y
        #pragma unroll
        for (int mt = 0; mt < 2; mt++) {
            #pragma unroll
            for (int half = 0; half < 2; half++) {
                int r = m0 + wm * 32 + mt * 16 + half * 8 + gg;
                if (r < cnt) {
                    int slot2 = off + r;
                    float wgt = g_pair_w[slot2];
                    size_t yrow = (size_t)slot2 * HID;
                    #pragma unroll
                    for (int nt = 0; nt < 8; nt++) {
                        int col = n0 + wn * 64 + nt * 8 + 2 * tt;
                        float y0 = wgt * (acc[mt][nt][half * 2 + 0] + b2e[col]);
                        float y1 = wgt * (acc[mt][nt][half * 2 + 1] + b2e[col + 1]);
                        *(float2*)&g_Y[yrow + col] = make_float2(y0, y1);
                    }
                }
            }
        }
        if (m0 + 256 < cnt) __syncthreads();
    }
}

// ---------------- launch ----------------
extern "C" void kernel_launch(void* const* d_in, const int* in_sizes, int n_in,
                              void* d_out, int out_size) {
    const float* x        = (const float*)d_in[0];
    const float* gate_w   = (const float*)d_in[1];
    const float* gate_b   = (const float*)d_in[2];
    const float* w1       = (const float*)d_in[3];
    const float* b1       = (const float*)d_in[4];
    const float* w2       = (const float*)d_in[5];
    const float* b2       = (const float*)d_in[6];
    const float* load_ema = (const float*)d_in[7];
    float* out = (float*)d_out;

    zero_kernel<<<1, 32>>>();
    router_kernel<<<NTOK, 256>>>(x, gate_w, gate_b);
    scan_aux_kernel<<<1, 32>>>(load_ema, out, out_size);
    scatter_kernel<<<NPAIR / 256, 256>>>();
    f1_kernel<<<dim3(FFN / 128, NEXP, 2), 256>>>(x, w1, b1);
    f2_kernel<<<dim3(HID / 128, NEXP, 2), 256>>>(w2, b2);
    combine_kernel<<<NTOK, 256>>>(out);
}

// round 9
// speedup vs baseline: 6.1411x; 1.3233x over previous
#include <cuda_runtime.h>
#include <cuda_bf16.h>
#include <math.h>
#include <stdint.h>

#define NTOK 1024
#define HID  1024
#define FFN  2048
#define NEXP 32
#define TOPK 4
#define NPAIR (NTOK*TOPK)

// ---------------- device scratch ----------------
static __device__ int      g_top_idx[NPAIR];
static __device__ float    g_top_w[NPAIR];
static __device__ float    g_logits[(size_t)NTOK * NEXP];
static __device__ int      g_cnt2[NEXP];
static __device__ int      g_off[NEXP + 1];
static __device__ int      g_pair_tok[NPAIR];
static __device__ float    g_pair_w[NPAIR];
static __device__ int      g_slot[NPAIR];
static __device__ uint32_t g_H[(size_t)NPAIR * FFN];  // packed (bf16 hi | bf16 lo<<16)
static __device__ float    g_Y[(size_t)NPAIR * HID];  // per-slot f2 output

// pipeline geometry
#define STAGES 4
#define ASW 2560   // words per A stage: 128 rows x 20 (16 data + 4 pad)
#define BSW 2112   // words per B stage: 16 rows x 132 (128 data + 4 pad)
#define SMEM_BYTES (STAGES * (ASW + BSW) * 4)   // 74752

__device__ __forceinline__ void mma16816(float* c, const uint32_t* a,
                                         uint32_t b0, uint32_t b1) {
    asm volatile(
        "mma.sync.aligned.m16n8k16.row.col.f32.bf16.bf16.f32 "
        "{%0,%1,%2,%3}, {%4,%5,%6,%7}, {%8,%9}, {%0,%1,%2,%3};\n"
        : "+f"(c[0]), "+f"(c[1]), "+f"(c[2]), "+f"(c[3])
        : "r"(a[0]), "r"(a[1]), "r"(a[2]), "r"(a[3]), "r"(b0), "r"(b1));
}
__device__ __forceinline__ void cp_ca(uint32_t d, const void* s) {
    asm volatile("cp.async.ca.shared.global [%0], [%1], 16;" :: "r"(d), "l"(s));
}
__device__ __forceinline__ void cp_cg(uint32_t d, const void* s) {
    asm volatile("cp.async.cg.shared.global [%0], [%1], 16;" :: "r"(d), "l"(s));
}
#define CP_COMMIT() asm volatile("cp.async.commit_group;" ::: "memory")
#define CP_WAIT2()  asm volatile("cp.async.wait_group 2;" ::: "memory")

// split: hi = truncated top16s (PRMT), residual exact -> bf16x2
__device__ __forceinline__ void split2t(float a, float b, uint32_t& h, uint32_t& l) {
    uint32_t ua = __float_as_uint(a), ub = __float_as_uint(b);
    h = __byte_perm(ua, ub, 0x7632);
    float ar = a - __uint_as_float(ua & 0xFFFF0000u);
    float br = b - __uint_as_float(ub & 0xFFFF0000u);
    asm("cvt.rn.bf16x2.f32 %0, %1, %2;" : "=r"(l) : "f"(br), "f"(ar));
}

// ---------------- router: logits + top-4 (no atomics) ----------------
__global__ __launch_bounds__(256) void router_kernel(const float* __restrict__ x,
                                                     const float* __restrict__ gw,
                                                     const float* __restrict__ gb) {
    __shared__ float xs[HID];
    __shared__ float ps[256];
    __shared__ float ls[NEXP];
    int t = blockIdx.x, tid = threadIdx.x;
    for (int i = tid; i < HID; i += 256) xs[i] = x[(size_t)t * HID + i];
    __syncthreads();
    int e = tid & 31, c = tid >> 5;
    int base = c * (HID / 8);
    float s = 0.0f;
    for (int i = 0; i < HID / 8; i++)
        s += xs[base + i] * gw[(size_t)(base + i) * NEXP + e];
    ps[tid] = s;
    __syncthreads();
    if (tid < NEXP) {
        float v = gb[tid];
        #pragma unroll
        for (int c2 = 0; c2 < 8; c2++) v += ps[c2 * 32 + tid];
        ls[tid] = v;
        g_logits[(size_t)t * NEXP + tid] = v;
    }
    __syncthreads();
    if (tid == 0) {
        float lv[NEXP];
        #pragma unroll
        for (int i = 0; i < NEXP; i++) lv[i] = ls[i];
        bool used[NEXP];
        #pragma unroll
        for (int i = 0; i < NEXP; i++) used[i] = false;
        int idx[TOPK]; float val[TOPK];
        for (int j = 0; j < TOPK; j++) {
            float best = -1e30f; int bi = 0;
            for (int i = 0; i < NEXP; i++)
                if (!used[i] && lv[i] > best) { best = lv[i]; bi = i; }
            used[bi] = true; idx[j] = bi; val[j] = best;
        }
        float m = val[0], se = 0.0f, w[TOPK];
        #pragma unroll
        for (int j = 0; j < TOPK; j++) { w[j] = expf(val[j] - m); se += w[j]; }
        #pragma unroll
        for (int j = 0; j < TOPK; j++) {
            g_top_idx[t * TOPK + j] = idx[j];
            g_top_w[t * TOPK + j] = w[j] / se;
        }
    }
}

// ---------------- scan: histogram + prefix + aux loss + cnt2 zero ----------------
__global__ __launch_bounds__(256) void scan_aux_kernel(const float* __restrict__ load_ema,
                                                       float* out, int out_size) {
    __shared__ int   cnts[NEXP];
    __shared__ float pm[NEXP];
    int tid = threadIdx.x;
    if (tid < NEXP) { cnts[tid] = 0; pm[tid] = 0.0f; }
    __syncthreads();
    for (int p = tid; p < NPAIR; p += 256)
        atomicAdd(&cnts[g_top_idx[p]], 1);
    float lpm[NEXP];
    #pragma unroll
    for (int i = 0; i < NEXP; i++) lpm[i] = 0.0f;
    for (int t = tid; t < NTOK; t += 256) {
        float lv[NEXP];
        float mm = -1e30f;
        #pragma unroll
        for (int i = 0; i < NEXP; i++) {
            lv[i] = g_logits[(size_t)t * NEXP + i];
            mm = fmaxf(mm, lv[i]);
        }
        float ss = 0.0f;
        #pragma unroll
        for (int i = 0; i < NEXP; i++) { lv[i] = expf(lv[i] - mm); ss += lv[i]; }
        #pragma unroll
        for (int i = 0; i < NEXP; i++) lpm[i] += lv[i] / ss;
    }
    #pragma unroll
    for (int i = 0; i < NEXP; i++) atomicAdd(&pm[i], lpm[i]);
    __syncthreads();
    if (tid == 0) {
        int off = 0;
        for (int e2 = 0; e2 < NEXP; e2++) { g_off[e2] = off; off += cnts[e2]; }
        g_off[NEXP] = off;
        float base_aux = 0.0f;
        for (int e2 = 0; e2 < NEXP; e2++)
            base_aux += ((float)cnts[e2] / (float)NPAIR) * (pm[e2] / (float)NTOK);
        base_aux *= (float)NEXP;
        float ssum = 0.0f;
        for (int e2 = 0; e2 < NEXP; e2++) ssum += load_ema[e2];
        float ent = 0.0f;
        for (int e2 = 0; e2 < NEXP; e2++) {
            float lp = load_ema[e2] / (ssum + 1e-8f);
            ent -= lp * logf(lp + 1e-8f);
        }
        float aux = base_aux + 0.001f * (logf((float)NEXP) - ent);
        if (out_size > NTOK * HID) out[NTOK * HID] = aux;
    }
    if (tid < NEXP) g_cnt2[tid] = 0;
}

__global__ void scatter_kernel() {
    int p = blockIdx.x * 256 + threadIdx.x;
    if (p >= NPAIR) return;
    int e = g_top_idx[p];
    int pos = g_off[e] + atomicAdd(&g_cnt2[e], 1);
    g_pair_tok[pos] = p >> 2;
    g_pair_w[pos] = g_top_w[p];
    g_slot[p] = pos;
}

__global__ __launch_bounds__(256) void combine_kernel(float* __restrict__ out) {
    int t = blockIdx.x;
    int s0 = g_slot[t * 4 + 0], s1 = g_slot[t * 4 + 1];
    int s2 = g_slot[t * 4 + 2], s3 = g_slot[t * 4 + 3];
    for (int c = threadIdx.x; c < HID; c += 256)
        out[(size_t)t * HID + c] = g_Y[(size_t)s0 * HID + c] + g_Y[(size_t)s1 * HID + c] +
                                   g_Y[(size_t)s2 * HID + c] + g_Y[(size_t)s3 * HID + c];
}

// ---------------- f1: H = gelu(Xg @ W1[e] + b1) -------------------------------
// grid (FFN/128, NEXP, 2), block 256 (8 warps: 4m x 2n), tile 128x128, kstep 16,
// 4-stage cp.async of RAW fp32; split to bf16 hi/lo at fragment load.
__global__ __launch_bounds__(256, 2) void f1_kernel(const float* __restrict__ x,
                                                    const float* __restrict__ w1,
                                                    const float* __restrict__ b1) {
    extern __shared__ float smf[];
    float* As = smf;                  // [STAGES][128*20]
    float* Bs = smf + STAGES * ASW;   // [STAGES][16*132]

    int e = blockIdx.y, z = blockIdx.z;
    int off = g_off[e], cnt = g_off[e + 1] - off;
    if (cnt == 0 || z * 128 >= cnt) return;

    int tid = threadIdx.x, lane = tid & 31, wid = tid >> 5;
    int wm = wid & 3, wn = wid >> 2;
    int gg = lane >> 2, tt = lane & 3;
    int n0 = blockIdx.x * 128;
    const float* w1e = w1 + (size_t)e * HID * FFN;
    const float* b1e = b1 + (size_t)e * FFN;

    uint32_t sbase = (uint32_t)__cvta_generic_to_shared(smf);
    uint32_t bbase_sm = sbase + STAGES * ASW * 4;

    // cp.async work split
    int arow = tid >> 1, ahalf = tid & 1;                  // A: 2 threads/row
    int bkk = tid >> 4, bc = 2 * (tid & 15);               // B: thread -> row bkk, col4 bc,bc+1
    uint32_t adst0 = sbase + (uint32_t)(arow * 20 + ahalf * 8) * 4;
    uint32_t bdst0 = bbase_sm + (uint32_t)(bkk * 132 + bc * 4) * 4;
    const float* bsrc0 = w1e + (size_t)bkk * FFN + n0 + bc * 4;

    const int NK = HID / 16;
    for (int m0 = z * 128; m0 < cnt; m0 += 256) {
        int slotA = off + min(m0 + arow, cnt - 1);
        const float* asrc0 = x + (size_t)g_pair_tok[slotA] * HID + ahalf * 8;

        float acc[2][8][4];
        #pragma unroll
        for (int i = 0; i < 2; i++)
            #pragma unroll
            for (int j = 0; j < 8; j++)
                #pragma unroll
                for (int k = 0; k < 4; k++) acc[i][j][k] = 0.0f;

        // prologue: stages 0..2
        #pragma unroll
        for (int s = 0; s < STAGES - 1; s++) {
            uint32_t ad = adst0 + (uint32_t)(s * ASW * 4);
            const float* as = asrc0 + s * 16;
            cp_ca(ad, as); cp_ca(ad + 16, as + 4);
            uint32_t bd = bdst0 + (uint32_t)(s * BSW * 4);
            const float* bs = bsrc0 + (size_t)(s * 16) * FFN;
            cp_cg(bd, bs); cp_cg(bd + 16, bs + 4);
            CP_COMMIT();
        }

        for (int kc = 0; kc < NK; kc++) {
            CP_WAIT2();
            __syncthreads();
            // issue stage kc+3 (writes slot (kc-1)&3: all readers done at last sync)
            if (kc + STAGES - 1 < NK) {
                int s = kc + STAGES - 1, sl = s & 3;
                uint32_t ad = adst0 + (uint32_t)(sl * ASW * 4);
                const float* as = asrc0 + s * 16;
                cp_ca(ad, as); cp_ca(ad + 16, as + 4);
                uint32_t bd = bdst0 + (uint32_t)(sl * BSW * 4);
                const float* bs = bsrc0 + (size_t)(s * 16) * FFN;
                cp_cg(bd, bs); cp_cg(bd + 16, bs + 4);
            }
            CP_COMMIT();

            int cur = kc & 3;
            const float* Ac = As + cur * ASW;
            const float* Bc = Bs + cur * BSW;

            uint32_t ah[2][4], al[2][4];
            #pragma unroll
            for (int mt = 0; mt < 2; mt++) {
                int mb = wm * 32 + mt * 16;
                float2 p0 = *(const float2*)&Ac[(mb + gg) * 20 + 2 * tt];
                float2 p1 = *(const float2*)&Ac[(mb + 8 + gg) * 20 + 2 * tt];
                float2 p2 = *(const float2*)&Ac[(mb + gg) * 20 + 8 + 2 * tt];
                float2 p3 = *(const float2*)&Ac[(mb + 8 + gg) * 20 + 8 + 2 * tt];
                split2t(p0.x, p0.y, ah[mt][0], al[mt][0]);
                split2t(p1.x, p1.y, ah[mt][1], al[mt][1]);
                split2t(p2.x, p2.y, ah[mt][2], al[mt][2]);
                split2t(p3.x, p3.y, ah[mt][3], al[mt][3]);
            }
            #pragma unroll
            for (int nt = 0; nt < 8; nt++) {
                int n = wn * 64 + nt * 8 + gg;
                uint32_t bh0, bl0, bh1, bl1;
                split2t(Bc[(2 * tt) * 132 + n], Bc[(2 * tt + 1) * 132 + n], bh0, bl0);
                split2t(Bc[(2 * tt + 8) * 132 + n], Bc[(2 * tt + 9) * 132 + n], bh1, bl1);
                #pragma unroll
                for (int mt = 0; mt < 2; mt++) {
                    mma16816(acc[mt][nt], ah[mt], bh0, bh1);
                    mma16816(acc[mt][nt], ah[mt], bl0, bl1);
                    mma16816(acc[mt][nt], al[mt], bh0, bh1);
                }
            }
        }

        // epilogue: bias + exact GELU -> packed bf16 hi/lo
        #pragma unroll
        for (int mt = 0; mt < 2; mt++) {
            #pragma unroll
            for (int half = 0; half < 2; half++) {
                int r = m0 + wm * 32 + mt * 16 + half * 8 + gg;
                if (r < cnt) {
                    size_t hrow = (size_t)(off + r) * FFN;
                    #pragma unroll
                    for (int nt = 0; nt < 8; nt++) {
                        int col = n0 + wn * 64 + nt * 8 + 2 * tt;
                        float2 bb = *(const float2*)&b1e[col];
                        float v0 = acc[mt][nt][half * 2 + 0] + bb.x;
                        float v1 = acc[mt][nt][half * 2 + 1] + bb.y;
                        float g0 = 0.5f * v0 * (1.0f + erff(v0 * 0.70710678118654752f));
                        float g1 = 0.5f * v1 * (1.0f + erff(v1 * 0.70710678118654752f));
                        uint32_t u0 = __float_as_uint(g0), u1 = __float_as_uint(g1);
                        float r0 = g0 - __uint_as_float(u0 & 0xFFFF0000u);
                        float r1 = g1 - __uint_as_float(u1 & 0xFFFF0000u);
                        uint32_t p0 = (u0 >> 16) |
                            ((uint32_t)__bfloat16_as_ushort(__float2bfloat16(r0)) << 16);
                        uint32_t p1 = (u1 >> 16) |
                            ((uint32_t)__bfloat16_as_ushort(__float2bfloat16(r1)) << 16);
                        *(uint2*)&g_H[hrow + col] = make_uint2(p0, p1);
                    }
                }
            }
        }
        __syncthreads();
    }
}

// ---------------- f2: Y[slot] = w * (H @ W2[e] + b2) --------------------------
// grid (HID/128, NEXP, 2), block 256; A = packed g_H (PRMT unpack), B = fp32 w2.
__global__ __launch_bounds__(256, 2) void f2_kernel(const float* __restrict__ w2,
                                                    const float* __restrict__ b2) {
    extern __shared__ float smf[];
    float* As = smf;
    float* Bs = smf + STAGES * ASW;

    int e = blockIdx.y, z = blockIdx.z;
    int off = g_off[e], cnt = g_off[e + 1] - off;
    if (cnt == 0 || z * 128 >= cnt) return;

    int tid = threadIdx.x, lane = tid & 31, wid = tid >> 5;
    int wm = wid & 3, wn = wid >> 2;
    int gg = lane >> 2, tt = lane & 3;
    int n0 = blockIdx.x * 128;
    const float* w2e = w2 + (size_t)e * FFN * HID;
    const float* b2e = b2 + (size_t)e * HID;

    uint32_t sbase = (uint32_t)__cvta_generic_to_shared(smf);
    uint32_t bbase_sm = sbase + STAGES * ASW * 4;

    int arow = tid >> 1, ahalf = tid & 1;
    int bkk = tid >> 4, bc = 2 * (tid & 15);
    uint32_t adst0 = sbase + (uint32_t)(arow * 20 + ahalf * 8) * 4;
    uint32_t bdst0 = bbase_sm + (uint32_t)(bkk * 132 + bc * 4) * 4;
    const float* bsrc0 = w2e + (size_t)bkk * HID + n0 + bc * 4;

    const int NK = FFN / 16;
    for (int m0 = z * 128; m0 < cnt; m0 += 256) {
        int slotA = off + min(m0 + arow, cnt - 1);
        const uint32_t* asrc0 = g_H + (size_t)slotA * FFN + ahalf * 8;

        float acc[2][8][4];
        #pragma unroll
        for (int i = 0; i < 2; i++)
            #pragma unroll
            for (int j = 0; j < 8; j++)
                #pragma unroll
                for (int k = 0; k < 4; k++) acc[i][j][k] = 0.0f;

        #pragma unroll
        for (int s = 0; s < STAGES - 1; s++) {
            uint32_t ad = adst0 + (uint32_t)(s * ASW * 4);
            const uint32_t* as = asrc0 + s * 16;
            cp_ca(ad, as); cp_ca(ad + 16, as + 4);
            uint32_t bd = bdst0 + (uint32_t)(s * BSW * 4);
            const float* bs = bsrc0 + (size_t)(s * 16) * HID;
            cp_cg(bd, bs); cp_cg(bd + 16, bs + 4);
            CP_COMMIT();
        }

        for (int kc = 0; kc < NK; kc++) {
            CP_WAIT2();
            __syncthreads();
            if (kc + STAGES - 1 < NK) {
                int s = kc + STAGES - 1, sl = s & 3;
                uint32_t ad = adst0 + (uint32_t)(sl * ASW * 4);
                const uint32_t* as = asrc0 + s * 16;
                cp_ca(ad, as); cp_ca(ad + 16, as + 4);
                uint32_t bd = bdst0 + (uint32_t)(sl * BSW * 4);
                const float* bs = bsrc0 + (size_t)(s * 16) * HID;
                cp_cg(bd, bs); cp_cg(bd + 16, bs + 4);
            }
            CP_COMMIT();

            int cur = kc & 3;
            const uint32_t* Ac = (const uint32_t*)(As + cur * ASW);
            const float* Bc = Bs + cur * BSW;

            uint32_t ah[2][4], al[2][4];
            #pragma unroll
            for (int mt = 0; mt < 2; mt++) {
                int mb = wm * 32 + mt * 16;
                uint2 q0 = *(const uint2*)&Ac[(mb + gg) * 20 + 2 * tt];
                uint2 q1 = *(const uint2*)&Ac[(mb + 8 + gg) * 20 + 2 * tt];
                uint2 q2 = *(const uint2*)&Ac[(mb + gg) * 20 + 8 + 2 * tt];
                uint2 q3 = *(const uint2*)&Ac[(mb + 8 + gg) * 20 + 8 + 2 * tt];
                ah[mt][0] = __byte_perm(q0.x, q0.y, 0x5410); al[mt][0] = __byte_perm(q0.x, q0.y, 0x7632);
                ah[mt][1] = __byte_perm(q1.x, q1.y, 0x5410); al[mt][1] = __byte_perm(q1.x, q1.y, 0x7632);
                ah[mt][2] = __byte_perm(q2.x, q2.y, 0x5410); al[mt][2] = __byte_perm(q2.x, q2.y, 0x7632);
                ah[mt][3] = __byte_perm(q3.x, q3.y, 0x5410); al[mt][3] = __byte_perm(q3.x, q3.y, 0x7632);
            }
            #pragma unroll
            for (int nt = 0; nt < 8; nt++) {
                int n = wn * 64 + nt * 8 + gg;
                uint32_t bh0, bl0, bh1, bl1;
                split2t(Bc[(2 * tt) * 132 + n], Bc[(2 * tt + 1) * 132 + n], bh0, bl0);
                split2t(Bc[(2 * tt + 8) * 132 + n], Bc[(2 * tt + 9) * 132 + n], bh1, bl1);
                #pragma unroll
                for (int mt = 0; mt < 2; mt++) {
                    mma16816(acc[mt][nt], ah[mt], bh0, bh1);
                    mma16816(acc[mt][nt], ah[mt], bl0, bl1);
                    mma16816(acc[mt][nt], al[mt], bh0, bh1);
                }
            }
        }

        #pragma unroll
        for (int mt = 0; mt < 2; mt++) {
            #pragma unroll
            for (int half = 0; half < 2; half++) {
                int r = m0 + wm * 32 + mt * 16 + half * 8 + gg;
                if (r < cnt) {
                    int slot2 = off + r;
                    float wgt = g_pair_w[slot2];
                    size_t yrow = (size_t)slot2 * HID;
                    #pragma unroll
                    for (int nt = 0; nt < 8; nt++) {
                        int col = n0 + wn * 64 + nt * 8 + 2 * tt;
                        float2 bb = *(const float2*)&b2e[col];
                        float y0 = wgt * (acc[mt][nt][half * 2 + 0] + bb.x);
                        float y1 = wgt * (acc[mt][nt][half * 2 + 1] + bb.y);
                        *(float2*)&g_Y[yrow + col] = make_float2(y0, y1);
                    }
                }
            }
        }
        __syncthreads();
    }
}

// ---------------- launch ----------------
extern "C" void kernel_launch(void* const* d_in, const int* in_sizes, int n_in,
                              void* d_out, int out_size) {
    const float* x        = (const float*)d_in[0];
    const float* gate_w   = (const float*)d_in[1];
    const float* gate_b   = (const float*)d_in[2];
    const float* w1       = (const float*)d_in[3];
    const float* b1       = (const float*)d_in[4];
    const float* w2       = (const float*)d_in[5];
    const float* b2       = (const float*)d_in[6];
    const float* load_ema = (const float*)d_in[7];
    float* out = (float*)d_out;

    cudaFuncSetAttribute(f1_kernel, cudaFuncAttributeMaxDynamicSharedMemorySize, SMEM_BYTES);
    cudaFuncSetAttribute(f2_kernel, cudaFuncAttributeMaxDynamicSharedMemorySize, SMEM_BYTES);

    router_kernel<<<NTOK, 256>>>(x, gate_w, gate_b);
    scan_aux_kernel<<<1, 256>>>(load_ema, out, out_size);
    scatter_kernel<<<NPAIR / 256, 256>>>();
    f1_kernel<<<dim3(FFN / 128, NEXP, 2), 256, SMEM_BYTES>>>(x, w1, b1);
    f2_kernel<<<dim3(HID / 128, NEXP, 2), 256, SMEM_BYTES>>>(w2, b2);
    combine_kernel<<<NTOK, 256>>>(out);
}